// round 15
// baseline (speedup 1.0000x reference)
#include <cuda_runtime.h>
#include <cuda_bf16.h>

#define NE 10
#define NBINS 11
#define THREADS 128
#define NWARP (THREADS / 32)
#define LOG2E 1.4426950408889634f
#define BOOST 120.0f

__device__ __forceinline__ float ex2f(float a) {
    float r; asm("ex2.approx.ftz.f32 %0, %1;" : "=f"(r) : "f"(a)); return r;
}
__device__ __forceinline__ float tanhf_hw(float a) {
    float r; asm("tanh.approx.f32 %0, %1;" : "=f"(r) : "f"(a)); return r;
}

__global__ __launch_bounds__(THREADS, 9)
void hist_prof_kernel(const float* __restrict__ x,
                      const float* __restrict__ edges,
                      float* __restrict__ out,
                      int hw, int C) {
    const int blk = blockIdx.x;          // blk = bt*C + c
    const int c = blk % C;
    const float* __restrict__ xp = x + (size_t)blk * hw;

    __shared__ float sE[NE];
    __shared__ float sred[NWARP][NBINS];

    if (threadIdx.x < NE) sE[threadIdx.x] = edges[(size_t)c * NE + threadIdx.x];
    __syncthreads();

    // ---- per-block constants (block-uniform -> UR-promotable) ----
    // anchors at the BOTTOM of each group: bin0 (mu0), bin1 (mu1), bin5 (mu5)
    const float mu0 = sE[0];
    const float mu1 = 0.5f * (sE[0] + sE[1]);
    const float mu2 = 0.5f * (sE[1] + sE[2]);
    const float mu5 = 0.5f * (sE[4] + sE[5]);
    const float mu6 = 0.5f * (sE[5] + sE[6]);
    const float sig = (sE[0] - sE[1]) * (1.0f / 3.0f) + 1e-6f;   // same all bins
    const float kk2 = (0.5f * LOG2E) / (sig * sig);    // G_i = 2^(-kk2 (x-mu_i)^2)
    const float nkk2 = -kk2;
    const float d   = mu2 - mu1;                       // uniform interior spacing

    // anchor quadratics: e_i = nkk2*x^2 + p_i*x + q_i  (shared x^2)
    const float p0c = 2.0f * kk2 * mu0, q0c = BOOST - kk2 * mu0 * mu0;
    const float p1c = 2.0f * kk2 * mu1, q1c = BOOST - kk2 * mu1 * mu1;
    const float p5c = 2.0f * kk2 * mu5, q5c = BOOST - kk2 * mu5 * mu5;

    // up-step ratios: R_{i->i+1} = 2^(a_up*x - kk2*d*(mu_i+mu_{i+1}))
    // One EX2 gives R12; all other steps are constant multiplies:
    //   R23 = R12*rho, R34 = R12*rho^2,   R56 = R12*c5, R67 = R56*rho, ...
    const float a_up = 2.0f * kk2 * d;
    const float b12  = -kk2 * d * (mu1 + mu2);
    const float b56  = -kk2 * d * (mu5 + mu6);
    const float rho  = exp2f(-2.0f * kk2 * d * d);     // per-extra-step decay
    const float c5   = exp2f(b56 - b12);               // R56 = R12 * c5 (~2^-52)
    const float inv  = exp2f(-BOOST);

    // upper clamp only: keeps R12 <= 2^125 (no inf -> no NaN products).
    // Low x needs no clamp: ratios/anchors underflow to 0, which is correct.
    const float xhi = (125.0f - b12) / a_up;    // ~ +1.1

    // sigmoid tail on RAW x via hw tanh:
    // sigmoid(20(x-e9)) = 0.5 + 0.5*tanh(10*(x-e9))
    const float tS = 10.0f;
    const float tB = -10.0f * sE[NE - 1];

    float a0 = 0.f, a1 = 0.f, a2 = 0.f, a3 = 0.f, a4 = 0.f;
    float a5 = 0.f, a6 = 0.f, a7 = 0.f, a8 = 0.f, a9 = 0.f, aS = 0.f;
    int pxcnt = 0;

#define DO_PX(xv_) do {                                                         \
        float xv = (xv_);                                                       \
        float xc = fminf(xv, xhi);                                              \
        float x2 = xc * xc;                                                     \
        /* three boosted anchors via shared x^2 */                              \
        float e0 = fmaf(x2, nkk2, fmaf(xc, p0c, q0c));                          \
        float e1 = fmaf(x2, nkk2, fmaf(xc, p1c, q1c));                          \
        float e5 = fmaf(x2, nkk2, fmaf(xc, p5c, q5c));                          \
        float G0 = ex2f(e0);                                                    \
        float G1 = ex2f(e1);                                                    \
        float G5 = ex2f(e5);                                                    \
        /* single ratio EX2; all other steps are constant muls */               \
        float R12 = ex2f(fmaf(xc, a_up, b12));                                  \
        a0 += G0;                                                               \
        /* group 1: anchor bin1; chain up 2,3,4 */                              \
        a1 += G1;                                                               \
        float g2 = G1 * R12;       a2 += g2;                                    \
        float r1 = R12 * rho;                                                   \
        float g3 = g2 * r1;        a3 += g3;                                    \
        r1 *= rho;                 a4 = fmaf(g3, r1, a4);                       \
        /* group 5: anchor bin5; chain up 6,7,8,9 */                            \
        a5 += G5;                                                               \
        float R56 = R12 * c5;                                                   \
        float g6 = G5 * R56;       a6 += g6;                                    \
        float r2 = R56 * rho;                                                   \
        float g7 = g6 * r2;        a7 += g7;                                    \
        r2 *= rho;                                                              \
        float g8 = g7 * r2;        a8 += g8;                                    \
        r2 *= rho;                 a9 = fmaf(g8, r2, a9);                       \
        /* sigmoid tail on raw x: accumulate tanh only */                       \
        aS += tanhf_hw(fmaf(xv, tS, tB));                                       \
    } while (0)

    // main loop: float4, coalesced, software-pipelined (prefetch next tile)
    const int n4 = hw >> 2;
    const float4* __restrict__ xp4 = (const float4*)xp;
    {
        int p = threadIdx.x;
        if (p < n4) {
            float4 v = xp4[p];
            for (;;) {
                const int pn = p + THREADS;
                const bool more = pn < n4;
                float4 vn = v;
                if (more) vn = xp4[pn];      // prefetch before the body
                DO_PX(v.x);
                DO_PX(v.y);
                DO_PX(v.z);
                DO_PX(v.w);
                if (!more) break;
                v = vn;
                p = pn;
            }
            pxcnt = 4 * ((n4 - (int)threadIdx.x + THREADS - 1) / THREADS);
        }
    }
    // tail (hw % 4; unused for hw=3136)
    for (int p = (n4 << 2) + threadIdx.x; p < hw; p += THREADS) {
        DO_PX(xp[p]);
        pxcnt++;
    }
#undef DO_PX

    // ---- reduction: unboost, shuffle, cross-warp smem ----
    // last bin: sum sigmoid = 0.5*(pxcnt + sum tanh)
    float accv[NBINS] = {a0, a1, a2, a3, a4, a5, a6, a7, a8, a9,
                         0.5f * ((float)pxcnt + aS)};
#pragma unroll
    for (int i = 0; i < NBINS; i++) {
        float v = (i < NE) ? accv[i] * inv : accv[i];
        v += __shfl_down_sync(0xFFFFFFFFu, v, 16);
        v += __shfl_down_sync(0xFFFFFFFFu, v, 8);
        v += __shfl_down_sync(0xFFFFFFFFu, v, 4);
        v += __shfl_down_sync(0xFFFFFFFFu, v, 2);
        v += __shfl_down_sync(0xFFFFFFFFu, v, 1);
        if ((threadIdx.x & 31) == 0) sred[threadIdx.x >> 5][i] = v;
    }
    __syncthreads();
    if (threadIdx.x < NBINS) {
        float s = 0.0f;
#pragma unroll
        for (int w = 0; w < NWARP; w++) s += sred[w][threadIdx.x];
        out[(size_t)blk * NBINS + threadIdx.x] = s;
    }
}

extern "C" void kernel_launch(void* const* d_in, const int* in_sizes, int n_in,
                              void* d_out, int out_size) {
    const float* x     = (const float*)d_in[0];
    const float* edges = (const float*)d_in[1];
    float* out = (float*)d_out;

    const int n_bc = out_size / NBINS;          // bt * c
    const int hw   = in_sizes[0] / n_bc;        // h * w
    const int C    = in_sizes[1] / NE;          // channels

    hist_prof_kernel<<<n_bc, THREADS>>>(x, edges, out, hw, C);
}

// round 16
// speedup vs baseline: 1.0587x; 1.0587x over previous
#include <cuda_runtime.h>
#include <cuda_bf16.h>

#define NE 10
#define NBINS 11
#define THREADS 128
#define NWARP (THREADS / 32)
#define LOG2E 1.4426950408889634f
#define BOOST 120.0f

__device__ __forceinline__ float ex2f(float a) {
    float r; asm("ex2.approx.ftz.f32 %0, %1;" : "=f"(r) : "f"(a)); return r;
}
__device__ __forceinline__ float tanhf_hw(float a) {
    float r; asm("tanh.approx.f32 %0, %1;" : "=f"(r) : "f"(a)); return r;
}

__global__ __launch_bounds__(THREADS, 9)
void hist_prof_kernel(const float* __restrict__ x,
                      const float* __restrict__ edges,
                      float* __restrict__ out,
                      int hw, int C) {
    const int blk = blockIdx.x;          // blk = bt*C + c
    const int c = blk % C;
    const float* __restrict__ xp = x + (size_t)blk * hw;

    __shared__ float sE[NE];
    __shared__ float sred[NWARP][NBINS];

    if (threadIdx.x < NE) sE[threadIdx.x] = edges[(size_t)c * NE + threadIdx.x];
    __syncthreads();

    // ---- per-block constants (block-uniform -> UR-promotable) ----
    // anchors at the BOTTOM of each group: bin0 (mu0), bin1 (mu1), bin5 (mu5)
    const float mu0 = sE[0];
    const float mu1 = 0.5f * (sE[0] + sE[1]);
    const float mu2 = 0.5f * (sE[1] + sE[2]);
    const float mu5 = 0.5f * (sE[4] + sE[5]);
    const float mu6 = 0.5f * (sE[5] + sE[6]);
    const float sig = (sE[0] - sE[1]) * (1.0f / 3.0f) + 1e-6f;   // same all bins
    const float kk2 = (0.5f * LOG2E) / (sig * sig);    // G_i = 2^(-kk2 (x-mu_i)^2)
    const float nkk2 = -kk2;
    const float d   = mu2 - mu1;                       // uniform interior spacing

    // anchor quadratics: e_i = nkk2*x^2 + p_i*x + q_i  (shared x^2)
    const float p0c = 2.0f * kk2 * mu0, q0c = BOOST - kk2 * mu0 * mu0;
    const float p1c = 2.0f * kk2 * mu1, q1c = BOOST - kk2 * mu1 * mu1;
    const float p5c = 2.0f * kk2 * mu5, q5c = BOOST - kk2 * mu5 * mu5;

    // up-step ratios: R_{i->i+1} = 2^(a_up*x - kk2*d*(mu_i+mu_{i+1}))
    const float a_up = 2.0f * kk2 * d;
    const float b12  = -kk2 * d * (mu1 + mu2);
    const float b56  = -kk2 * d * (mu5 + mu6);
    const float rho  = exp2f(-2.0f * kk2 * d * d);     // per-extra-step decay
    const float c5   = exp2f(b56 - b12);               // R56 = R12 * c5
    const float inv  = exp2f(-BOOST);

    // upper clamp only: keeps R12 <= 2^125 (no inf -> no NaN products);
    // low x underflows cleanly to 0 everywhere.
    const float xhi = (125.0f - b12) / a_up;    // ~ +1.1

    // sigmoid tail on RAW x via hw tanh: sigmoid(20(x-e9)) = 0.5 + 0.5*tanh(10(x-e9))
    const float tS = 10.0f;
    const float tB = -10.0f * sE[NE - 1];

    float a0 = 0.f, a1 = 0.f, a2 = 0.f, a3 = 0.f, a4 = 0.f;
    float a5 = 0.f, a6 = 0.f, a7 = 0.f, a8 = 0.f, a9 = 0.f, aS = 0.f;
    int pxcnt = 0;

#define DO_PX(xv_) do {                                                         \
        float xv = (xv_);                                                       \
        float xc = fminf(xv, xhi);                                              \
        float x2 = xc * xc;                                                     \
        float e0 = fmaf(x2, nkk2, fmaf(xc, p0c, q0c));                          \
        float e1 = fmaf(x2, nkk2, fmaf(xc, p1c, q1c));                          \
        float e5 = fmaf(x2, nkk2, fmaf(xc, p5c, q5c));                          \
        float G0 = ex2f(e0);                                                    \
        float G1 = ex2f(e1);                                                    \
        float G5 = ex2f(e5);                                                    \
        float R12 = ex2f(fmaf(xc, a_up, b12));                                  \
        a0 += G0;                                                               \
        a1 += G1;                                                               \
        float g2 = G1 * R12;       a2 += g2;                                    \
        float r1 = R12 * rho;                                                   \
        float g3 = g2 * r1;        a3 += g3;                                    \
        r1 *= rho;                 a4 = fmaf(g3, r1, a4);                       \
        a5 += G5;                                                               \
        float R56 = R12 * c5;                                                   \
        float g6 = G5 * R56;       a6 += g6;                                    \
        float r2 = R56 * rho;                                                   \
        float g7 = g6 * r2;        a7 += g7;                                    \
        r2 *= rho;                                                              \
        float g8 = g7 * r2;        a8 += g8;                                    \
        r2 *= rho;                 a9 = fmaf(g8, r2, a9);                       \
        aS += tanhf_hw(fmaf(xv, tS, tB));                                       \
    } while (0)

#define DO_F4(v) do { DO_PX((v).x); DO_PX((v).y); DO_PX((v).z); DO_PX((v).w); } while (0)

    // main loop: 3 float4 per iteration, front-batched loads (MLP=3),
    // no conditional copies / BSSY in the hot path; residual loop after.
    const int n4 = hw >> 2;
    const float4* __restrict__ xp4 = (const float4*)xp;
    int p = threadIdx.x;
    for (; p + 2 * THREADS < n4; p += 3 * THREADS) {
        float4 v0 = xp4[p];
        float4 v1 = xp4[p + THREADS];
        float4 v2 = xp4[p + 2 * THREADS];
        DO_F4(v0);
        DO_F4(v1);
        DO_F4(v2);
    }
    for (; p < n4; p += THREADS) {
        float4 v = xp4[p];
        DO_F4(v);
    }
    if ((int)threadIdx.x < n4)
        pxcnt = 4 * ((n4 - (int)threadIdx.x + THREADS - 1) / THREADS);
    // tail (hw % 4; unused for hw=3136)
    for (int q = (n4 << 2) + threadIdx.x; q < hw; q += THREADS) {
        DO_PX(xp[q]);
        pxcnt++;
    }
#undef DO_F4
#undef DO_PX

    // ---- reduction: unboost, shuffle, cross-warp smem ----
    // last bin: sum sigmoid = 0.5*(pxcnt + sum tanh)
    float accv[NBINS] = {a0, a1, a2, a3, a4, a5, a6, a7, a8, a9,
                         0.5f * ((float)pxcnt + aS)};
#pragma unroll
    for (int i = 0; i < NBINS; i++) {
        float v = (i < NE) ? accv[i] * inv : accv[i];
        v += __shfl_down_sync(0xFFFFFFFFu, v, 16);
        v += __shfl_down_sync(0xFFFFFFFFu, v, 8);
        v += __shfl_down_sync(0xFFFFFFFFu, v, 4);
        v += __shfl_down_sync(0xFFFFFFFFu, v, 2);
        v += __shfl_down_sync(0xFFFFFFFFu, v, 1);
        if ((threadIdx.x & 31) == 0) sred[threadIdx.x >> 5][i] = v;
    }
    __syncthreads();
    if (threadIdx.x < NBINS) {
        float s = 0.0f;
#pragma unroll
        for (int w = 0; w < NWARP; w++) s += sred[w][threadIdx.x];
        out[(size_t)blk * NBINS + threadIdx.x] = s;
    }
}

extern "C" void kernel_launch(void* const* d_in, const int* in_sizes, int n_in,
                              void* d_out, int out_size) {
    const float* x     = (const float*)d_in[0];
    const float* edges = (const float*)d_in[1];
    float* out = (float*)d_out;

    const int n_bc = out_size / NBINS;          // bt * c
    const int hw   = in_sizes[0] / n_bc;        // h * w
    const int C    = in_sizes[1] / NE;          // channels

    hist_prof_kernel<<<n_bc, THREADS>>>(x, edges, out, hw, C);
}